// round 1
// baseline (speedup 1.0000x reference)
#include <cuda_runtime.h>

#define BATCH   16
#define KPTS    2048
#define NPOINT  2048
#define TPB_A   256
#define CHUNK   256                  // points-i per CTA in kernel A
#define CTAS_PER_BATCH (KPTS / CHUNK) // 8

// scratch for per-point kNN values (no allocations allowed)
__device__ float g_value[BATCH * KPTS];

// ---------------------------------------------------------------------------
// Kernel A: per-point mean distance to 2 nearest neighbors (self excluded).
// grid = (8, 16), 256 threads. Each CTA loads all 2048 points of its batch
// into shared as float4 (x, y, z, |p|^2); each thread owns one point i and
// scans all j. d'(i,j) = sq_j - 2*dot(pi,pj) via a 3-FFMA chain using
// per-thread pre-scaled (-2x_i, -2y_i, -2z_i); sq_i added back at the end.
// Self-exclusion via loop split at j == i (no per-j compare).
// ---------------------------------------------------------------------------
__global__ __launch_bounds__(TPB_A)
void sor_knn_value_kernel(const float* __restrict__ x) {
    __shared__ float4 sp[KPTS];   // (x, y, z, sq)

    const int b   = blockIdx.y;
    const int tid = threadIdx.x;
    const float* __restrict__ xb = x + b * 3 * KPTS;

    // stage points: coalesced global loads, separate-product sq (matches
    // reference's sum(pc*pc) rounding shape)
    for (int t = tid; t < KPTS; t += TPB_A) {
        float px = xb[t];
        float py = xb[KPTS + t];
        float pz = xb[2 * KPTS + t];
        float sq = __fadd_rn(__fadd_rn(__fmul_rn(px, px), __fmul_rn(py, py)),
                             __fmul_rn(pz, pz));
        sp[t] = make_float4(px, py, pz, sq);
    }
    __syncthreads();

    const int i = blockIdx.x * CHUNK + tid;
    const float4 me = sp[i];
    const float ax = -2.0f * me.x;
    const float ay = -2.0f * me.y;
    const float az = -2.0f * me.z;
    const float si = me.w;

    float m1 = 3.402823466e38f;   // smallest d'
    float m2 = 3.402823466e38f;   // second smallest d'

    // j in [0, i)
    #pragma unroll 8
    for (int j = 0; j < i; ++j) {
        float4 p = sp[j];
        float d = __fmaf_rn(p.x, ax, p.w);
        d = __fmaf_rn(p.y, ay, d);
        d = __fmaf_rn(p.z, az, d);
        float t = fmaxf(m1, d);
        m1 = fminf(m1, d);
        m2 = fminf(m2, t);
    }
    // j in (i, KPTS)
    #pragma unroll 8
    for (int j = i + 1; j < KPTS; ++j) {
        float4 p = sp[j];
        float d = __fmaf_rn(p.x, ax, p.w);
        d = __fmaf_rn(p.y, ay, d);
        d = __fmaf_rn(p.z, az, d);
        float t = fmaxf(m1, d);
        m1 = fminf(m1, d);
        m2 = fminf(m2, t);
    }

    // value = mean of the two nearest squared distances (d = d' + sq_i)
    g_value[b * KPTS + i] = (__fadd_rn(m1, si) + __fadd_rn(m2, si)) * 0.5f;
}

// ---------------------------------------------------------------------------
// Kernel B: per-batch stats + stable compaction + tiled gather.
// grid = 16, 256 threads, one CTA per batch.
// ---------------------------------------------------------------------------
__global__ __launch_bounds__(256)
void sor_compact_gather_kernel(const float* __restrict__ x,
                               float* __restrict__ out) {
    __shared__ float sx[KPTS];
    __shared__ float sy[KPTS];
    __shared__ float sz[KPTS];
    __shared__ float sval[KPTS];
    __shared__ int   skept[KPTS];
    __shared__ float red[8];
    __shared__ int   wofs[8];
    __shared__ float s_mean, s_thr;
    __shared__ int   s_n;

    const int b   = blockIdx.x;
    const int tid = threadIdx.x;
    const int lane = tid & 31;
    const int warp = tid >> 5;
    const float* __restrict__ xb = x + b * 3 * KPTS;
    float* __restrict__ ob = out + b * 3 * KPTS;

    for (int t = tid; t < KPTS; t += 256) {
        sx[t] = xb[t];
        sy[t] = xb[KPTS + t];
        sz[t] = xb[2 * KPTS + t];
        sval[t] = g_value[b * KPTS + t];
    }
    __syncthreads();

    // ---- mean ----
    float s = 0.0f;
    for (int t = tid; t < KPTS; t += 256) s += sval[t];
    #pragma unroll
    for (int o = 16; o; o >>= 1) s += __shfl_xor_sync(0xffffffffu, s, o);
    if (lane == 0) red[warp] = s;
    __syncthreads();
    if (tid == 0) {
        float tot = 0.0f;
        #pragma unroll
        for (int w = 0; w < 8; ++w) tot += red[w];
        s_mean = tot * (1.0f / (float)KPTS);
    }
    __syncthreads();
    const float mean = s_mean;

    // ---- std (ddof = 1) ----
    float s2 = 0.0f;
    for (int t = tid; t < KPTS; t += 256) {
        float d = sval[t] - mean;
        s2 = __fmaf_rn(d, d, s2);
    }
    #pragma unroll
    for (int o = 16; o; o >>= 1) s2 += __shfl_xor_sync(0xffffffffu, s2, o);
    if (lane == 0) red[warp] = s2;
    __syncthreads();
    if (tid == 0) {
        float tot = 0.0f;
        #pragma unroll
        for (int w = 0; w < 8; ++w) tot += red[w];
        float var = tot / (float)(KPTS - 1);
        // threshold = mean + 1.1 * std, no fma contraction (match reference)
        s_thr = __fadd_rn(mean, __fmul_rn(1.1f, sqrtf(var)));
    }
    __syncthreads();
    const float thr = s_thr;

    // ---- stable compaction: thread owns a contiguous block of 8 indices ----
    const int base_t = tid * 8;
    unsigned mbits = 0;
    int c = 0;
    #pragma unroll
    for (int u = 0; u < 8; ++u) {
        bool m = sval[base_t + u] <= thr;
        mbits |= (unsigned)m << u;
        c += (int)m;
    }
    // inclusive scan of counts within warp
    int v = c;
    #pragma unroll
    for (int o = 1; o < 32; o <<= 1) {
        int t2 = __shfl_up_sync(0xffffffffu, v, o);
        if (lane >= o) v += t2;
    }
    if (lane == 31) wofs[warp] = v;   // warp totals (temporarily)
    __syncthreads();
    if (tid == 0) {
        int acc = 0;
        #pragma unroll
        for (int w = 0; w < 8; ++w) {
            int t3 = wofs[w];
            wofs[w] = acc;
            acc += t3;
        }
        s_n = acc;
    }
    __syncthreads();
    int pos = (v - c) + wofs[warp];   // exclusive prefix for this thread
    #pragma unroll
    for (int u = 0; u < 8; ++u) {
        if ((mbits >> u) & 1u) skept[pos++] = base_t + u;
    }
    __syncthreads();

    // ---- tiled gather: out[:, j] = pts[kept[j mod n]] ----
    const int n = s_n;   // >= 1 always (min value <= mean <= threshold)
    for (int j = tid; j < NPOINT; j += 256) {
        int p = (j < n) ? j : (j % n);
        int idx = skept[p];
        ob[j]            = sx[idx];
        ob[KPTS + j]     = sy[idx];
        ob[2 * KPTS + j] = sz[idx];
    }
}

extern "C" void kernel_launch(void* const* d_in, const int* in_sizes, int n_in,
                              void* d_out, int out_size) {
    (void)in_sizes; (void)n_in; (void)out_size;
    const float* x = (const float*)d_in[0];
    float* out = (float*)d_out;

    sor_knn_value_kernel<<<dim3(CTAS_PER_BATCH, BATCH), TPB_A>>>(x);
    sor_compact_gather_kernel<<<BATCH, 256>>>(x, out);
}

// round 2
// speedup vs baseline: 1.1109x; 1.1109x over previous
#include <cuda_runtime.h>

#define BATCH   16
#define KPTS    2048
#define NPOINT  2048
#define TPB_A   256
#define IBLK    2
#define ICHUNK  (TPB_A * IBLK)        // 512 i-points per CTA
#define NI_CH   (KPTS / ICHUNK)       // 4
#define JS      4                     // j-splits
#define JCH     (KPTS / JS)           // 512 j-points per CTA
#define TPB_B   512
#define NWARP_B (TPB_B / 32)          // 16
#define ELEMS_B (KPTS / TPB_B)        // 4 mask elements per thread
#define FLT_BIG 3.402823466e38f

// partial top-2 (as true squared distances, +sq_i applied) per (batch, j-chunk, i)
__device__ float2 g_part[BATCH * JS * KPTS];

__device__ __forceinline__ void knn_step(float4 p, float ax, float ay, float az,
                                         float& m1, float& m2) {
    float d = __fmaf_rn(p.x, ax, p.w);
    d = __fmaf_rn(p.y, ay, d);
    d = __fmaf_rn(p.z, az, d);
    float t = fmaxf(m1, d);
    m1 = fminf(m1, d);
    m2 = fminf(m2, t);
}

// ---------------------------------------------------------------------------
// Kernel A: partial 2-NN over one j-chunk for 512 i-points (2 per thread).
// grid = (NI_CH, JS, BATCH) = 256 CTAs, 256 threads, 8KB smem.
// ---------------------------------------------------------------------------
__global__ __launch_bounds__(TPB_A)
void sor_knn_partial_kernel(const float* __restrict__ x) {
    __shared__ float4 sp[JCH];   // (x, y, z, |p|^2) for this j-chunk

    const int b   = blockIdx.z;
    const int ci  = blockIdx.x;
    const int cj  = blockIdx.y;
    const int tid = threadIdx.x;
    const float* __restrict__ xb = x + b * 3 * KPTS;
    const int jlo = cj * JCH;

    #pragma unroll
    for (int t = tid; t < JCH; t += TPB_A) {
        int g = jlo + t;
        float px = xb[g];
        float py = xb[KPTS + g];
        float pz = xb[2 * KPTS + g];
        float sq = __fadd_rn(__fadd_rn(__fmul_rn(px, px), __fmul_rn(py, py)),
                             __fmul_rn(pz, pz));
        sp[t] = make_float4(px, py, pz, sq);
    }
    __syncthreads();

    const int i0 = ci * ICHUNK + tid;
    const int i1 = i0 + TPB_A;

    float x0 = xb[i0], y0 = xb[KPTS + i0], z0 = xb[2 * KPTS + i0];
    float x1 = xb[i1], y1 = xb[KPTS + i1], z1 = xb[2 * KPTS + i1];
    const float ax0 = -2.0f * x0, ay0 = -2.0f * y0, az0 = -2.0f * z0;
    const float ax1 = -2.0f * x1, ay1 = -2.0f * y1, az1 = -2.0f * z1;
    const float si0 = __fadd_rn(__fadd_rn(__fmul_rn(x0, x0), __fmul_rn(y0, y0)),
                                __fmul_rn(z0, z0));
    const float si1 = __fadd_rn(__fadd_rn(__fmul_rn(x1, x1), __fmul_rn(y1, y1)),
                                __fmul_rn(z1, z1));

    float m1a = FLT_BIG, m2a = FLT_BIG;
    float m1b = FLT_BIG, m2b = FLT_BIG;

    if (ci == cj) {
        // diagonal CTA: both i0 and i1 lie in this j-chunk; split loops per acc
        const int l0 = tid;             // local index of i0
        const int l1 = tid + TPB_A;     // local index of i1
        #pragma unroll 4
        for (int j = 0; j < l0; ++j)        knn_step(sp[j], ax0, ay0, az0, m1a, m2a);
        #pragma unroll 4
        for (int j = l0 + 1; j < JCH; ++j)  knn_step(sp[j], ax0, ay0, az0, m1a, m2a);
        #pragma unroll 4
        for (int j = 0; j < l1; ++j)        knn_step(sp[j], ax1, ay1, az1, m1b, m2b);
        #pragma unroll 4
        for (int j = l1 + 1; j < JCH; ++j)  knn_step(sp[j], ax1, ay1, az1, m1b, m2b);
    } else {
        // off-diagonal: clean fused loop, one LDS feeds both accumulators
        #pragma unroll 8
        for (int j = 0; j < JCH; ++j) {
            float4 p = sp[j];
            knn_step(p, ax0, ay0, az0, m1a, m2a);
            knn_step(p, ax1, ay1, az1, m1b, m2b);
        }
    }

    float2* __restrict__ gp = g_part + (b * JS + cj) * KPTS;
    gp[i0] = make_float2(__fadd_rn(m1a, si0), __fadd_rn(m2a, si0));
    gp[i1] = make_float2(__fadd_rn(m1b, si1), __fadd_rn(m2b, si1));
}

// ---------------------------------------------------------------------------
// Kernel B: merge partials -> value, per-batch stats, stable compaction,
// tiled gather. grid = 16, 512 threads.
// ---------------------------------------------------------------------------
__global__ __launch_bounds__(TPB_B)
void sor_compact_gather_kernel(const float* __restrict__ x,
                               float* __restrict__ out) {
    __shared__ float sx[KPTS];
    __shared__ float sy[KPTS];
    __shared__ float sz[KPTS];
    __shared__ float sval[KPTS];
    __shared__ int   skept[KPTS];
    __shared__ float red[NWARP_B];
    __shared__ int   wofs[NWARP_B];
    __shared__ float s_mean, s_thr;
    __shared__ int   s_n;

    const int b    = blockIdx.x;
    const int tid  = threadIdx.x;
    const int lane = tid & 31;
    const int warp = tid >> 5;
    const float* __restrict__ xb = x + b * 3 * KPTS;
    float* __restrict__ ob = out + b * 3 * KPTS;

    // stage points + merge JS partial top-2's into the final kNN mean value
    #pragma unroll
    for (int t = tid; t < KPTS; t += TPB_B) {
        sx[t] = xb[t];
        sy[t] = xb[KPTS + t];
        sz[t] = xb[2 * KPTS + t];
        float m1 = FLT_BIG, m2 = FLT_BIG;
        #pragma unroll
        for (int c = 0; c < JS; ++c) {
            float2 pr = g_part[(b * JS + c) * KPTS + t];
            float t1 = fmaxf(m1, pr.x);
            m1 = fminf(m1, pr.x);
            m2 = fminf(m2, t1);
            float t2 = fmaxf(m1, pr.y);
            m1 = fminf(m1, pr.y);
            m2 = fminf(m2, t2);
        }
        sval[t] = __fadd_rn(m1, m2) * 0.5f;
    }
    __syncthreads();

    // ---- mean ----
    float s = 0.0f;
    #pragma unroll
    for (int t = tid; t < KPTS; t += TPB_B) s += sval[t];
    #pragma unroll
    for (int o = 16; o; o >>= 1) s += __shfl_xor_sync(0xffffffffu, s, o);
    if (lane == 0) red[warp] = s;
    __syncthreads();
    if (tid == 0) {
        float tot = 0.0f;
        #pragma unroll
        for (int w = 0; w < NWARP_B; ++w) tot += red[w];
        s_mean = tot * (1.0f / (float)KPTS);
    }
    __syncthreads();
    const float mean = s_mean;

    // ---- std (ddof = 1) ----
    float s2 = 0.0f;
    #pragma unroll
    for (int t = tid; t < KPTS; t += TPB_B) {
        float d = sval[t] - mean;
        s2 = __fmaf_rn(d, d, s2);
    }
    #pragma unroll
    for (int o = 16; o; o >>= 1) s2 += __shfl_xor_sync(0xffffffffu, s2, o);
    if (lane == 0) red[warp] = s2;
    __syncthreads();
    if (tid == 0) {
        float tot = 0.0f;
        #pragma unroll
        for (int w = 0; w < NWARP_B; ++w) tot += red[w];
        float var = tot / (float)(KPTS - 1);
        s_thr = __fadd_rn(mean, __fmul_rn(1.1f, sqrtf(var)));
    }
    __syncthreads();
    const float thr = s_thr;

    // ---- stable compaction: thread owns ELEMS_B contiguous indices ----
    const int base_t = tid * ELEMS_B;
    unsigned mbits = 0;
    int c = 0;
    #pragma unroll
    for (int u = 0; u < ELEMS_B; ++u) {
        bool m = sval[base_t + u] <= thr;
        mbits |= (unsigned)m << u;
        c += (int)m;
    }
    int v = c;
    #pragma unroll
    for (int o = 1; o < 32; o <<= 1) {
        int t2 = __shfl_up_sync(0xffffffffu, v, o);
        if (lane >= o) v += t2;
    }
    if (lane == 31) wofs[warp] = v;
    __syncthreads();
    if (tid == 0) {
        int acc = 0;
        #pragma unroll
        for (int w = 0; w < NWARP_B; ++w) {
            int t3 = wofs[w];
            wofs[w] = acc;
            acc += t3;
        }
        s_n = acc;
    }
    __syncthreads();
    int pos = (v - c) + wofs[warp];
    #pragma unroll
    for (int u = 0; u < ELEMS_B; ++u) {
        if ((mbits >> u) & 1u) skept[pos++] = base_t + u;
    }
    __syncthreads();

    // ---- tiled gather: out[:, j] = pts[kept[j mod n]] ----
    const int n = s_n;   // >= 1 always
    #pragma unroll
    for (int j = tid; j < NPOINT; j += TPB_B) {
        int p = (j < n) ? j : (j % n);
        int idx = skept[p];
        ob[j]            = sx[idx];
        ob[KPTS + j]     = sy[idx];
        ob[2 * KPTS + j] = sz[idx];
    }
}

extern "C" void kernel_launch(void* const* d_in, const int* in_sizes, int n_in,
                              void* d_out, int out_size) {
    (void)in_sizes; (void)n_in; (void)out_size;
    const float* x = (const float*)d_in[0];
    float* out = (float*)d_out;

    sor_knn_partial_kernel<<<dim3(NI_CH, JS, BATCH), TPB_A>>>(x);
    sor_compact_gather_kernel<<<BATCH, TPB_B>>>(x, out);
}

// round 3
// speedup vs baseline: 1.3873x; 1.2488x over previous
#include <cuda_runtime.h>

#define BATCH   16
#define KPTS    2048
#define NPOINT  2048

#define TPB_A   256
#define IBLK    2
#define ICHUNK  (TPB_A * IBLK)        // 512 i-points per CTA
#define NI_CH   (KPTS / ICHUNK)       // 4
#define JS      8                     // j-splits
#define JCH     (KPTS / JS)           // 256 j-points per CTA (== TPB_A)

#define TPB_B1  1024
#define NWARP_B (TPB_B1 / 32)         // 32
#define ELEMS_B (KPTS / TPB_B1)       // 2 mask elements per thread
#define FLT_BIG 3.402823466e38f

// partial top-2 (true squared distances, +sq_i applied) per (batch, j-chunk, i)
__device__ float2 g_part[BATCH * JS * KPTS];
// merged per-point kNN mean value
__device__ float  g_value[BATCH * KPTS];

__device__ __forceinline__ void knn_step(float4 p, float ax, float ay, float az,
                                         float& m1, float& m2) {
    float d = __fmaf_rn(p.x, ax, p.w);
    d = __fmaf_rn(p.y, ay, d);
    d = __fmaf_rn(p.z, az, d);
    float t = fmaxf(m1, d);
    m1 = fminf(m1, d);
    m2 = fminf(m2, t);
}

// ---------------------------------------------------------------------------
// Kernel A: partial 2-NN over one 256-point j-chunk for 512 i-points
// (2 per thread). grid = (4, 8, 16) = 512 CTAs, 256 threads, 4KB smem.
// Each diagonal CTA contains exactly one self-point, for exactly one of the
// two accumulators -> two fused ranges + one singleton step.
// ---------------------------------------------------------------------------
__global__ __launch_bounds__(TPB_A)
void sor_knn_partial_kernel(const float* __restrict__ x) {
    __shared__ float4 sp[JCH];   // (x, y, z, |p|^2) for this j-chunk

    const int b   = blockIdx.z;
    const int ci  = blockIdx.x;
    const int cj  = blockIdx.y;
    const int tid = threadIdx.x;
    const float* __restrict__ xb = x + b * 3 * KPTS;
    const int jlo = cj * JCH;

    {   // stage j-chunk (one element per thread: JCH == TPB_A)
        int g = jlo + tid;
        float px = xb[g];
        float py = xb[KPTS + g];
        float pz = xb[2 * KPTS + g];
        float sq = __fadd_rn(__fadd_rn(__fmul_rn(px, px), __fmul_rn(py, py)),
                             __fmul_rn(pz, pz));
        sp[tid] = make_float4(px, py, pz, sq);
    }
    __syncthreads();

    const int i0 = ci * ICHUNK + tid;
    const int i1 = i0 + TPB_A;

    float x0 = xb[i0], y0 = xb[KPTS + i0], z0 = xb[2 * KPTS + i0];
    float x1 = xb[i1], y1 = xb[KPTS + i1], z1 = xb[2 * KPTS + i1];
    const float ax0 = -2.0f * x0, ay0 = -2.0f * y0, az0 = -2.0f * z0;
    const float ax1 = -2.0f * x1, ay1 = -2.0f * y1, az1 = -2.0f * z1;
    const float si0 = __fadd_rn(__fadd_rn(__fmul_rn(x0, x0), __fmul_rn(y0, y0)),
                                __fmul_rn(z0, z0));
    const float si1 = __fadd_rn(__fadd_rn(__fmul_rn(x1, x1), __fmul_rn(y1, y1)),
                                __fmul_rn(z1, z1));

    float m1a = FLT_BIG, m2a = FLT_BIG;
    float m1b = FLT_BIG, m2b = FLT_BIG;

    // which accumulator's self point lies in this j-chunk (if any)?
    // i0 lives in j-chunk 2*ci, i1 in j-chunk 2*ci+1, local index == tid.
    const int selfacc = (cj == 2 * ci) ? 0 : ((cj == 2 * ci + 1) ? 1 : -1);

    if (selfacc < 0) {
        #pragma unroll 8
        for (int j = 0; j < JCH; ++j) {
            float4 p = sp[j];
            knn_step(p, ax0, ay0, az0, m1a, m2a);
            knn_step(p, ax1, ay1, az1, m1b, m2b);
        }
    } else {
        const int l = tid;
        #pragma unroll 4
        for (int j = 0; j < l; ++j) {
            float4 p = sp[j];
            knn_step(p, ax0, ay0, az0, m1a, m2a);
            knn_step(p, ax1, ay1, az1, m1b, m2b);
        }
        {   // singleton: apply only to the accumulator whose self this is NOT
            float4 p = sp[l];
            if (selfacc == 0) knn_step(p, ax1, ay1, az1, m1b, m2b);
            else              knn_step(p, ax0, ay0, az0, m1a, m2a);
        }
        #pragma unroll 4
        for (int j = l + 1; j < JCH; ++j) {
            float4 p = sp[j];
            knn_step(p, ax0, ay0, az0, m1a, m2a);
            knn_step(p, ax1, ay1, az1, m1b, m2b);
        }
    }

    float2* __restrict__ gp = g_part + (b * JS + cj) * KPTS;
    gp[i0] = make_float2(__fadd_rn(m1a, si0), __fadd_rn(m2a, si0));
    gp[i1] = make_float2(__fadd_rn(m1b, si1), __fadd_rn(m2b, si1));
}

// ---------------------------------------------------------------------------
// Kernel B0: merge JS partial top-2's -> per-point kNN mean value.
// grid = 128 CTAs x 256 threads, one point per thread, 8 independent loads.
// ---------------------------------------------------------------------------
__global__ __launch_bounds__(256)
void sor_merge_kernel() {
    const int g = blockIdx.x * 256 + threadIdx.x;   // [0, BATCH*KPTS)
    const int b = g >> 11;
    const int i = g & (KPTS - 1);

    float m1 = FLT_BIG, m2 = FLT_BIG;
    #pragma unroll
    for (int c = 0; c < JS; ++c) {
        float2 pr = g_part[(b * JS + c) * KPTS + i];
        float t1 = fmaxf(m1, pr.x);
        m1 = fminf(m1, pr.x);
        m2 = fminf(m2, t1);
        float t2 = fmaxf(m1, pr.y);
        m1 = fminf(m1, pr.y);
        m2 = fminf(m2, t2);
    }
    g_value[g] = __fadd_rn(m1, m2) * 0.5f;
}

// ---------------------------------------------------------------------------
// Kernel B1: per-batch stats + stable compaction + tiled gather.
// grid = 16, 1024 threads, one CTA per batch.
// ---------------------------------------------------------------------------
__global__ __launch_bounds__(TPB_B1)
void sor_compact_gather_kernel(const float* __restrict__ x,
                               float* __restrict__ out) {
    __shared__ float sx[KPTS];
    __shared__ float sy[KPTS];
    __shared__ float sz[KPTS];
    __shared__ float sval[KPTS];
    __shared__ int   skept[KPTS];
    __shared__ float red[NWARP_B];
    __shared__ int   wofs[NWARP_B];
    __shared__ float s_mean, s_thr;
    __shared__ int   s_n;

    const int b    = blockIdx.x;
    const int tid  = threadIdx.x;
    const int lane = tid & 31;
    const int warp = tid >> 5;
    const float* __restrict__ xb = x + b * 3 * KPTS;
    float* __restrict__ ob = out + b * 3 * KPTS;

    #pragma unroll
    for (int t = tid; t < KPTS; t += TPB_B1) {
        sx[t]   = xb[t];
        sy[t]   = xb[KPTS + t];
        sz[t]   = xb[2 * KPTS + t];
        sval[t] = g_value[b * KPTS + t];
    }
    __syncthreads();

    // ---- mean ----
    float s = 0.0f;
    #pragma unroll
    for (int t = tid; t < KPTS; t += TPB_B1) s += sval[t];
    #pragma unroll
    for (int o = 16; o; o >>= 1) s += __shfl_xor_sync(0xffffffffu, s, o);
    if (lane == 0) red[warp] = s;
    __syncthreads();
    if (warp == 0) {
        float v = red[lane];
        #pragma unroll
        for (int o = 16; o; o >>= 1) v += __shfl_xor_sync(0xffffffffu, v, o);
        if (lane == 0) s_mean = v * (1.0f / (float)KPTS);
    }
    __syncthreads();
    const float mean = s_mean;

    // ---- std (ddof = 1) ----
    float s2 = 0.0f;
    #pragma unroll
    for (int t = tid; t < KPTS; t += TPB_B1) {
        float d = sval[t] - mean;
        s2 = __fmaf_rn(d, d, s2);
    }
    #pragma unroll
    for (int o = 16; o; o >>= 1) s2 += __shfl_xor_sync(0xffffffffu, s2, o);
    if (lane == 0) red[warp] = s2;
    __syncthreads();
    if (warp == 0) {
        float v = red[lane];
        #pragma unroll
        for (int o = 16; o; o >>= 1) v += __shfl_xor_sync(0xffffffffu, v, o);
        if (lane == 0) {
            float var = v / (float)(KPTS - 1);
            s_thr = __fadd_rn(s_mean, __fmul_rn(1.1f, sqrtf(var)));
        }
    }
    __syncthreads();
    const float thr = s_thr;

    // ---- stable compaction: thread owns ELEMS_B contiguous indices ----
    const int base_t = tid * ELEMS_B;
    unsigned mbits = 0;
    int c = 0;
    #pragma unroll
    for (int u = 0; u < ELEMS_B; ++u) {
        bool m = sval[base_t + u] <= thr;
        mbits |= (unsigned)m << u;
        c += (int)m;
    }
    int v = c;
    #pragma unroll
    for (int o = 1; o < 32; o <<= 1) {
        int t2 = __shfl_up_sync(0xffffffffu, v, o);
        if (lane >= o) v += t2;
    }
    if (lane == 31) wofs[warp] = v;    // warp totals
    __syncthreads();
    if (warp == 0) {
        int wv = wofs[lane];
        int inc = wv;
        #pragma unroll
        for (int o = 1; o < 32; o <<= 1) {
            int t3 = __shfl_up_sync(0xffffffffu, inc, o);
            if (lane >= o) inc += t3;
        }
        wofs[lane] = inc - wv;          // exclusive warp offsets
        if (lane == 31) s_n = inc;      // total kept
    }
    __syncthreads();
    int pos = (v - c) + wofs[warp];
    #pragma unroll
    for (int u = 0; u < ELEMS_B; ++u) {
        if ((mbits >> u) & 1u) skept[pos++] = base_t + u;
    }
    __syncthreads();

    // ---- tiled gather: out[:, j] = pts[kept[j mod n]] ----
    const int n = s_n;   // >= 1 always
    #pragma unroll
    for (int j = tid; j < NPOINT; j += TPB_B1) {
        int p = (j < n) ? j : (j % n);
        int idx = skept[p];
        ob[j]            = sx[idx];
        ob[KPTS + j]     = sy[idx];
        ob[2 * KPTS + j] = sz[idx];
    }
}

extern "C" void kernel_launch(void* const* d_in, const int* in_sizes, int n_in,
                              void* d_out, int out_size) {
    (void)in_sizes; (void)n_in; (void)out_size;
    const float* x = (const float*)d_in[0];
    float* out = (float*)d_out;

    sor_knn_partial_kernel<<<dim3(NI_CH, JS, BATCH), TPB_A>>>(x);
    sor_merge_kernel<<<(BATCH * KPTS) / 256, 256>>>();
    sor_compact_gather_kernel<<<BATCH, TPB_B1>>>(x, out);
}